// round 14
// baseline (speedup 1.0000x reference)
#include <cuda_runtime.h>
#include <cuda_fp16.h>
#include <cstdint>

#define N_SEQ 512
#define D_IN 64
#define D_HID 128
#define LN_EPS 1e-5f
constexpr size_t R_TOT = (size_t)N_SEQ * N_SEQ;   // 262144

// ---------------- scratch (static device globals — allocation-free) ----------
__device__ __half g_a[(size_t)D_HID * R_TOT];    // [c][i*N+k]  fp16
__device__ __half g_b[(size_t)D_HID * R_TOT];    // [c][j*N+k]
__device__ __half g_gate[R_TOT * D_IN];          // [row][64]   post-sigmoid fp16
__device__ __half g_op[(size_t)D_HID * R_TOT];   // [c][i*N+j]  fp16

// ---------------- helpers ----------------------------------------------------
__device__ __forceinline__ float tf32f(float x){
    uint32_t u = __float_as_uint(x);
    asm("cvt.rna.tf32.f32 %0, %0;" : "+r"(u));
    return __uint_as_float(u);
}
__device__ __forceinline__ void mma8(float* d, const uint32_t* a, const uint32_t* b){
    asm volatile("mma.sync.aligned.m16n8k8.row.col.f32.tf32.tf32.f32 "
        "{%0,%1,%2,%3}, {%4,%5,%6,%7}, {%8,%9}, {%0,%1,%2,%3};"
        : "+f"(d[0]), "+f"(d[1]), "+f"(d[2]), "+f"(d[3])
        : "r"(a[0]), "r"(a[1]), "r"(a[2]), "r"(a[3]), "r"(b[0]), "r"(b[1]));
}
// fp16 mma, fp32 accumulate
__device__ __forceinline__ void mma16(float* d, uint32_t a0, uint32_t a1, uint32_t a2,
                                      uint32_t a3, uint32_t b0, uint32_t b1){
    asm volatile("mma.sync.aligned.m16n8k16.row.col.f32.f16.f16.f32 "
        "{%0,%1,%2,%3}, {%4,%5,%6,%7}, {%8,%9}, {%0,%1,%2,%3};"
        : "+f"(d[0]), "+f"(d[1]), "+f"(d[2]), "+f"(d[3])
        : "r"(a0), "r"(a1), "r"(a2), "r"(a3), "r"(b0), "r"(b1));
}
// sigmoid via 1 MUFU: sig(x) = 0.5*tanh(0.5x) + 0.5
__device__ __forceinline__ float sigmoid_f(float x){
    float t; asm("tanh.approx.f32 %0, %1;" : "=f"(t) : "f"(0.5f*x));
    return fmaf(0.5f, t, 0.5f);
}
__device__ __forceinline__ void cp16(uint32_t s, const void* g){
    asm volatile("cp.async.cg.shared.global [%0], [%1], 16;"
                 :: "r"(s), "l"(__cvta_generic_to_global(g)) : "memory");
}

// ============================================================================
// K1: fused LN(z) + h @ [Wp|Wg|Wgate] + p*sigmoid(g).  fp16 mma (m16n8k16).
// SMEM:
//   Zst (fp32 z staging, dbuf) 2 x [64][68]      = 34816 B @ 0
//   Wsm (fp16 weights) [ch2][576][32]            = 73728 B @ 34816
//   Hsm (fp16 h, dbuf) [buf2][ch2][64][32]       = 16384 B @ 108544
//   Esm (fp16 pg staging) [256][72]              = 36864 B @ 124928
// Epilogue: pg -> Esm (STS.16, conflict-free pattern), sync, then coalesced
// 64B-per-channel vector stores (LDS.128 phases hit all 32 banks; stride 36
// words == 4 mod 32 + seg offset 16).
// ============================================================================
#define K1_SMEM 161792
#define ESTRIDE 72

__device__ __forceinline__ void k1_load_z(uint32_t smb, const float* z, int tile, int buf, int t){
    const int lr = t >> 3, lsub = t & 7;
    uint32_t dst = smb + (uint32_t)((buf*64*68 + lr*68 + lsub*8)*4);
    const float* src = z + (size_t)(tile*64 + lr)*D_IN + lsub*8;
    cp16(dst, src);
    cp16(dst + 16, src + 4);
    asm volatile("cp.async.commit_group;" ::: "memory");
}

__global__ void __launch_bounds__(512,1) k1_proj(
    const float* __restrict__ z, const float* __restrict__ lnw, const float* __restrict__ lnb,
    const float* __restrict__ Wp, const float* __restrict__ Wg, const float* __restrict__ Wgate)
{
    extern __shared__ char smc[];
    float*  Zst = (float*)smc;                    // [buf][64][68]
    __half* Wsm = (__half*)(smc + 34816);         // [ch][576][32]
    __half* Hsm = (__half*)(smc + 108544);        // [buf][ch][64][32]
    __half* Esm = (__half*)(smc + 124928);        // [256][ESTRIDE]
    const uint32_t smb = (uint32_t)__cvta_generic_to_shared(smc);
    const int t = threadIdx.x;
    const int NT = (int)(R_TOT/64);

    // preload weights (fp16), column-tile interleave: even 8-tiles=Wp, odd=Wg,
    // tiles 64..71 = Wgate; chunked layout.
    for (int idx = t; idx < 576*D_IN; idx += 512){
        int k = idx / 576, n = idx - k*576;
        int T = n >> 3, ct = n & 7;
        float v;
        if (T < 64){
            int col = (T>>1)*8 + ct;
            v = (T & 1) ? Wg[k*256 + col] : Wp[k*256 + col];
        } else {
            v = Wgate[k*64 + (T-64)*8 + ct];
        }
        Wsm[(k>>5)*18432 + n*32 + (k&31)] = __float2half_rn(v);
    }

    const int lane = t & 31, w = t >> 5;
    const int wr = w >> 3, wc = w & 7;          // 2 warp-rows x 8 warp-cols
    const int grp = lane >> 2, tg = lane & 3;
    const int lr = t >> 3, lsub = t & 7;        // LN: 8 threads / row
    const float lw0 = __ldg(lnw+lsub*8+0), lw1 = __ldg(lnw+lsub*8+1),
                lw2 = __ldg(lnw+lsub*8+2), lw3 = __ldg(lnw+lsub*8+3),
                lw4 = __ldg(lnw+lsub*8+4), lw5 = __ldg(lnw+lsub*8+5),
                lw6 = __ldg(lnw+lsub*8+6), lw7 = __ldg(lnw+lsub*8+7);
    const float lb0 = __ldg(lnb+lsub*8+0), lb1 = __ldg(lnb+lsub*8+1),
                lb2 = __ldg(lnb+lsub*8+2), lb3 = __ldg(lnb+lsub*8+3),
                lb4 = __ldg(lnb+lsub*8+4), lb5 = __ldg(lnb+lsub*8+5),
                lb6 = __ldg(lnb+lsub*8+6), lb7 = __ldg(lnb+lsub*8+7);

    // store-phase constants
    const int sc  = t >> 1;                     // channel 0..255
    const int seg = t & 1;                      // 32-half segment
    __half* gdst_base = (sc < D_HID) ? (g_a + (size_t)sc*R_TOT)
                                     : (g_b + (size_t)(sc-D_HID)*R_TOT);

    int buf = 0;
    if ((int)blockIdx.x < NT) k1_load_z(smb, z, blockIdx.x, 0, t);

    for (int tile = blockIdx.x; tile < NT; tile += gridDim.x, buf ^= 1){
        const int row0 = tile * 64;
        asm volatile("cp.async.wait_group 0;" ::: "memory");

        // ---- LayerNorm own 8 elements -> fp16 chunked Hsm ----
        {
            const float* zp = Zst + buf*64*68 + lr*68 + lsub*8;
            float4 v0 = *(const float4*)zp;
            float4 v1 = *(const float4*)(zp + 4);
            float s = v0.x+v0.y+v0.z+v0.w + v1.x+v1.y+v1.z+v1.w;
            float q = v0.x*v0.x+v0.y*v0.y+v0.z*v0.z+v0.w*v0.w
                    + v1.x*v1.x+v1.y*v1.y+v1.z*v1.z+v1.w*v1.w;
            s += __shfl_xor_sync(0xffffffffu, s, 1); q += __shfl_xor_sync(0xffffffffu, q, 1);
            s += __shfl_xor_sync(0xffffffffu, s, 2); q += __shfl_xor_sync(0xffffffffu, q, 2);
            s += __shfl_xor_sync(0xffffffffu, s, 4); q += __shfl_xor_sync(0xffffffffu, q, 4);
            float mu = s * (1.0f/64.0f);
            float rstd = rsqrtf(q*(1.0f/64.0f) - mu*mu + LN_EPS);
            __half2 h0 = __floats2half2_rn((v0.x-mu)*rstd*lw0 + lb0, (v0.y-mu)*rstd*lw1 + lb1);
            __half2 h1 = __floats2half2_rn((v0.z-mu)*rstd*lw2 + lb2, (v0.w-mu)*rstd*lw3 + lb3);
            __half2 h2 = __floats2half2_rn((v1.x-mu)*rstd*lw4 + lb4, (v1.y-mu)*rstd*lw5 + lb5);
            __half2 h3 = __floats2half2_rn((v1.z-mu)*rstd*lw6 + lb6, (v1.w-mu)*rstd*lw7 + lb7);
            __half2* hp = (__half2*)(Hsm + buf*4096 + (lsub>>2)*2048 + lr*32 + (lsub&3)*8);
            hp[0] = h0; hp[1] = h1; hp[2] = h2; hp[3] = h3;
        }
        __syncthreads();

        // prefetch next tile while mma runs
        int ntile = tile + gridDim.x;
        if (ntile < NT) k1_load_z(smb, z, ntile, buf^1, t);

        float acc[9][2][4];
        #pragma unroll
        for (int a1=0;a1<9;a1++)
            #pragma unroll
            for (int a2=0;a2<2;a2++)
                #pragma unroll
                for (int a3=0;a3<4;a3++) acc[a1][a2][a3]=0.f;

        const int mbase = wr*32;
        const __half* Hb = Hsm + buf*4096;
        #pragma unroll
        for (int ch=0; ch<2; ch++){
            const __half* Ha = Hb + ch*2048;
            uint4 alo[2], ahi[2];
            #pragma unroll
            for (int ms=0; ms<2; ms++){
                alo[ms] = *(const uint4*)(Ha + (mbase + ms*16 + grp)*32 + tg*8);
                ahi[ms] = *(const uint4*)(Ha + (mbase + ms*16 + 8 + grp)*32 + tg*8);
            }
            #pragma unroll
            for (int nt=0; nt<9; nt++){
                const int tileN = (nt<8) ? (wc*8+nt) : (64+wc);
                uint4 bv = *(const uint4*)(Wsm + ch*18432 + (tileN*8 + grp)*32 + tg*8);
                #pragma unroll
                for (int ms=0; ms<2; ms++){
                    mma16(acc[nt][ms], alo[ms].x, ahi[ms].x, alo[ms].y, ahi[ms].y, bv.x, bv.y);
                    mma16(acc[nt][ms], alo[ms].z, ahi[ms].z, alo[ms].w, ahi[ms].w, bv.z, bv.w);
                }
            }
        }

        // ---- epilogue: pg = P*sig(G) -> Esm (smem staging) ----
        #pragma unroll
        for (int pp=0; pp<4; pp++){
            const int colb = (wc*4+pp)*8 + tg*2;   // 0..255 over [a|b] channels
            #pragma unroll
            for (int ms=0; ms<2; ms++){
                #pragma unroll
                for (int e=0; e<4; e++){
                    float av = acc[2*pp][ms][e] * sigmoid_f(acc[2*pp+1][ms][e]);
                    int col  = colb + (e&1);
                    int rloc = mbase + ms*16 + grp + ((e>>1)<<3);
                    Esm[col*ESTRIDE + rloc] = __float2half_rn(av);
                }
            }
        }
        // gate: direct global half2 (row-major, contiguous pair)
        #pragma unroll
        for (int ms=0; ms<2; ms++){
            const int col = wc*8 + tg*2;
            const int rb = row0 + mbase + ms*16 + grp;
            __half2 h0 = __floats2half2_rn(sigmoid_f(acc[8][ms][0]), sigmoid_f(acc[8][ms][1]));
            __half2 h1 = __floats2half2_rn(sigmoid_f(acc[8][ms][2]), sigmoid_f(acc[8][ms][3]));
            *(__half2*)(g_gate + (size_t)rb*D_IN + col)     = h0;
            *(__half2*)(g_gate + (size_t)(rb+8)*D_IN + col) = h1;
        }
        __syncthreads();

        // ---- store phase: coalesced 64B per (channel, segment) ----
        {
            const uint4* src = (const uint4*)(Esm + sc*ESTRIDE + seg*32);
            __half* dst = gdst_base + row0 + seg*32;
            uint4 v0 = src[0], v1 = src[1], v2 = src[2], v3 = src[3];
            *(uint4*)(dst)      = v0;
            *(uint4*)(dst + 8)  = v1;
            *(uint4*)(dst + 16) = v2;
            *(uint4*)(dst + 24) = v3;
        }
    }
}

// ============================================================================
// K2: per-channel NT GEMM OP_c = A_c @ B_c^T in fp16 (fp32 accumulate).
// 128x128x32 stages, 256 threads, 2 CTA/SM, double-buffered cp.async.
// (layout/permutation proof: see prior rounds — verified passing)
// ============================================================================
#define K2_STAGE_H 8192
#define K2_SMEM (2*K2_STAGE_H*2)             // 32768 B

__device__ __forceinline__ void k2_load(uint32_t smb, const __half* Ag, const __half* Bg,
                                        int t, int kt, int buf){
    const int kb = kt*32;
    const uint32_t base = smb + (uint32_t)(buf*K2_STAGE_H*2);
    #pragma unroll
    for (int s=0; s<2; s++){
        int idx = t + s*256;
        int r = idx >> 2, ci = idx & 3;
        cp16(base + (uint32_t)(r*64 + ci*16),
             Ag + (size_t)r*N_SEQ + kb + ci*8);
    }
    #pragma unroll
    for (int s=0; s<2; s++){
        int idx = t + s*256;
        int r = idx >> 2, ci = idx & 3;
        cp16(base + 8192u + (uint32_t)(r*64 + ci*16),
             Bg + (size_t)r*N_SEQ + kb + ci*8);
    }
    asm volatile("cp.async.commit_group;" ::: "memory");
}

__global__ void __launch_bounds__(256,2) k2_tri()
{
    extern __shared__ __half smh[];
    const uint32_t smb = (uint32_t)__cvta_generic_to_shared(smh);
    const int c  = blockIdx.y;
    const int i0 = (blockIdx.x >> 2) * 128;
    const int j0 = (blockIdx.x & 3) * 128;
    const __half* Ag = g_a + (size_t)c*R_TOT + (size_t)i0*N_SEQ;
    const __half* Bg = g_b + (size_t)c*R_TOT + (size_t)j0*N_SEQ;

    const int t = threadIdx.x, lane = t & 31, w = t >> 5;
    const int grp = lane >> 2, tg = lane & 3;
    const int wm = (w >> 2) * 64, wn = (w & 3) * 32;

    float acc[4][4][4];
    #pragma unroll
    for (int a1=0;a1<4;a1++)
        #pragma unroll
        for (int a2=0;a2<4;a2++)
            #pragma unroll
            for (int a3=0;a3<4;a3++) acc[a1][a2][a3]=0.f;

    k2_load(smb, Ag, Bg, t, 0, 0);

    for (int kt = 0; kt < 16; kt++){
        const int buf = kt & 1;
        asm volatile("cp.async.wait_group 0;" ::: "memory");
        __syncthreads();
        if (kt < 15) k2_load(smb, Ag, Bg, t, kt+1, buf^1);

        const __half* As = smh + buf*K2_STAGE_H;
        const __half* Bs = As + 4096;

        uint4 bv[4];
        #pragma unroll
        for (int ns=0; ns<4; ns++)
            bv[ns] = *(const uint4*)(Bs + (wn + ns*8 + grp)*32 + tg*8);

        #pragma unroll
        for (int ms=0; ms<4; ms++){
            uint4 alo = *(const uint4*)(As + (wm + ms*16 + grp)*32 + tg*8);
            uint4 ahi = *(const uint4*)(As + (wm + ms*16 + 8 + grp)*32 + tg*8);
            #pragma unroll
            for (int ns=0; ns<4; ns++){
                mma16(acc[ms][ns], alo.x, ahi.x, alo.y, ahi.y, bv[ns].x, bv[ns].y);
                mma16(acc[ms][ns], alo.z, ahi.z, alo.w, ahi.w, bv[ns].z, bv[ns].w);
            }
        }
    }

    // epilogue: g_op[c][i][j] fp16
    #pragma unroll
    for (int ms=0; ms<4; ms++){
        #pragma unroll
        for (int ns=0; ns<4; ns++){
            size_t base = (size_t)c*R_TOT + (size_t)(i0+wm+ms*16+grp)*N_SEQ + (j0+wn+ns*8+tg*2);
            *(__half2*)(g_op + base)           = __floats2half2_rn(acc[ms][ns][0], acc[ms][ns][1]);
            *(__half2*)(g_op + base + 8*N_SEQ) = __floats2half2_rn(acc[ms][ns][2], acc[ms][ns][3]);
        }
    }
}

// ============================================================================
// K3: transpose 128pos x 128chan tile, LN over channels, @Wout (tf32 mma),
//     * gate (fp16), write final output.  g_op is fp16.
// ============================================================================
#define K3PAD 132
#define K3_SMEM ((128*K3PAD + 64*K3PAD)*4)   // 101376

__global__ void __launch_bounds__(256,2) k3_out(
    const float* __restrict__ lnow, const float* __restrict__ lnob,
    const float* __restrict__ Wout, float* __restrict__ outp)
{
    extern __shared__ float sm[];
    float* Op = sm;                   // [128 pos][K3PAD] channels contiguous
    float* Wsm = sm + 128*K3PAD;      // [64 n][K3PAD] k contiguous
    const int t = threadIdx.x;
    const int pos0 = blockIdx.x * 128;

    for (int idx = t; idx < 64*128; idx += 256){
        int k = idx >> 6, n = idx & 63;
        Wsm[n*K3PAD + k] = tf32f(Wout[k*64 + n]);
    }
    for (int idx = t; idx < 128*64; idx += 256){
        int c = idx >> 6, p2 = (idx & 63)*2;
        float2 v = __half22float2(*(const __half2*)(g_op + (size_t)c*R_TOT + pos0 + p2));
        Op[p2*K3PAD + c]     = v.x;
        Op[(p2+1)*K3PAD + c] = v.y;
    }
    __syncthreads();

    {
        const int r = t >> 1, h = t & 1;
        float* base = Op + r*K3PAD + h*64;
        float s = 0.f, q = 0.f;
        #pragma unroll
        for (int j=0; j<16; j++){
            float4 v = *(float4*)(base + j*4);
            s += v.x+v.y+v.z+v.w;
            q += v.x*v.x+v.y*v.y+v.z*v.z+v.w*v.w;
        }
        s += __shfl_xor_sync(0xffffffffu, s, 1);
        q += __shfl_xor_sync(0xffffffffu, q, 1);
        float mu = s * (1.0f/128.0f);
        float rstd = rsqrtf(q*(1.0f/128.0f) - mu*mu + LN_EPS);
        #pragma unroll
        for (int j=0; j<16; j++){
            float4 v = *(float4*)(base + j*4);
            int cb = h*64 + j*4;
            v.x = tf32f((v.x-mu)*rstd*__ldg(lnow+cb+0) + __ldg(lnob+cb+0));
            v.y = tf32f((v.y-mu)*rstd*__ldg(lnow+cb+1) + __ldg(lnob+cb+1));
            v.z = tf32f((v.z-mu)*rstd*__ldg(lnow+cb+2) + __ldg(lnob+cb+2));
            v.w = tf32f((v.w-mu)*rstd*__ldg(lnow+cb+3) + __ldg(lnob+cb+3));
            *(float4*)(base + j*4) = v;
        }
    }
    __syncthreads();

    const int lane = t & 31, w = t >> 5;
    const int grp = lane >> 2, tg = lane & 3;
    float acc[8][4];
    #pragma unroll
    for (int a1=0;a1<8;a1++)
        #pragma unroll
        for (int a3=0;a3<4;a3++) acc[a1][a3]=0.f;

    #pragma unroll
    for (int kc=0; kc<16; kc++){
        const int kb = kc*8 + tg;
        const float* pa = Op + (w*16 + grp)*K3PAD + kb;
        uint32_t af[4] = {
            __float_as_uint(pa[0]),
            __float_as_uint(pa[8*K3PAD]),
            __float_as_uint(pa[4]),
            __float_as_uint(pa[8*K3PAD+4])
        };
        #pragma unroll
        for (int nt=0; nt<8; nt++){
            const float* pb = Wsm + (nt*8 + grp)*K3PAD + kb;
            uint32_t bf[2] = {__float_as_uint(pb[0]), __float_as_uint(pb[4])};
            mma8(acc[nt], af, bf);
        }
    }

    #pragma unroll
    for (int nt=0; nt<8; nt++){
        const int colb = nt*8 + tg*2;
        const int r0 = pos0 + w*16 + grp;
        float2 gv0 = __half22float2(*(const __half2*)(g_gate + (size_t)r0*D_IN + colb));
        float2 gv1 = __half22float2(*(const __half2*)(g_gate + (size_t)(r0+8)*D_IN + colb));
        float2 o0 = {acc[nt][0]*gv0.x, acc[nt][1]*gv0.y};
        float2 o1 = {acc[nt][2]*gv1.x, acc[nt][3]*gv1.y};
        *(float2*)(outp + (size_t)r0*D_IN + colb)     = o0;
        *(float2*)(outp + (size_t)(r0+8)*D_IN + colb) = o1;
    }
}

// ============================================================================
extern "C" void kernel_launch(void* const* d_in, const int* in_sizes, int n_in,
                              void* d_out, int out_size) {
    (void)in_sizes; (void)n_in; (void)out_size;
    const float* z     = (const float*)d_in[0];
    const float* lniw  = (const float*)d_in[1];
    const float* lnib  = (const float*)d_in[2];
    const float* Wp    = (const float*)d_in[3];
    const float* Wg    = (const float*)d_in[4];
    const float* lnow  = (const float*)d_in[5];
    const float* lnob  = (const float*)d_in[6];
    const float* Wout  = (const float*)d_in[7];
    const float* Wgate = (const float*)d_in[8];
    float* outp = (float*)d_out;

    cudaFuncSetAttribute(k1_proj, cudaFuncAttributeMaxDynamicSharedMemorySize, K1_SMEM);
    cudaFuncSetAttribute(k2_tri,  cudaFuncAttributeMaxDynamicSharedMemorySize, K2_SMEM);
    cudaFuncSetAttribute(k3_out,  cudaFuncAttributeMaxDynamicSharedMemorySize, K3_SMEM);

    k1_proj<<<148, 512, K1_SMEM>>>(z, lniw, lnib, Wp, Wg, Wgate);
    k2_tri<<<dim3(16,128,1), 256, K2_SMEM>>>();
    k3_out<<<2048, 256, K3_SMEM>>>(lnow, lnob, Wout, outp);
}

// round 16
// speedup vs baseline: 1.0293x; 1.0293x over previous
#include <cuda_runtime.h>
#include <cuda_fp16.h>
#include <cstdint>

// R16 resubmission of R15 (container flake; source re-audited, unchanged).

#define N_SEQ 512
#define D_IN 64
#define D_HID 128
#define LN_EPS 1e-5f
constexpr size_t R_TOT = (size_t)N_SEQ * N_SEQ;   // 262144

// ---------------- scratch (static device globals — allocation-free) ----------
__device__ __half g_a[(size_t)D_HID * R_TOT];    // [c][i*N+k]  fp16
__device__ __half g_b[(size_t)D_HID * R_TOT];    // [c][j*N+k]
__device__ __half g_gate[R_TOT * D_IN];          // [row][64]   post-sigmoid fp16
__device__ __half g_op[(size_t)D_HID * R_TOT];   // [c][i*N+j]  fp16

// ---------------- helpers ----------------------------------------------------
__device__ __forceinline__ float tf32f(float x){
    uint32_t u = __float_as_uint(x);
    asm("cvt.rna.tf32.f32 %0, %0;" : "+r"(u));
    return __uint_as_float(u);
}
__device__ __forceinline__ void mma8(float* d, const uint32_t* a, const uint32_t* b){
    asm volatile("mma.sync.aligned.m16n8k8.row.col.f32.tf32.tf32.f32 "
        "{%0,%1,%2,%3}, {%4,%5,%6,%7}, {%8,%9}, {%0,%1,%2,%3};"
        : "+f"(d[0]), "+f"(d[1]), "+f"(d[2]), "+f"(d[3])
        : "r"(a[0]), "r"(a[1]), "r"(a[2]), "r"(a[3]), "r"(b[0]), "r"(b[1]));
}
// fp16 mma, fp32 accumulate
__device__ __forceinline__ void mma16(float* d, uint32_t a0, uint32_t a1, uint32_t a2,
                                      uint32_t a3, uint32_t b0, uint32_t b1){
    asm volatile("mma.sync.aligned.m16n8k16.row.col.f32.f16.f16.f32 "
        "{%0,%1,%2,%3}, {%4,%5,%6,%7}, {%8,%9}, {%0,%1,%2,%3};"
        : "+f"(d[0]), "+f"(d[1]), "+f"(d[2]), "+f"(d[3])
        : "r"(a0), "r"(a1), "r"(a2), "r"(a3), "r"(b0), "r"(b1));
}
// sigmoid via 1 MUFU: sig(x) = 0.5*tanh(0.5x) + 0.5
__device__ __forceinline__ float sigmoid_f(float x){
    float t; asm("tanh.approx.f32 %0, %1;" : "=f"(t) : "f"(0.5f*x));
    return fmaf(0.5f, t, 0.5f);
}
__device__ __forceinline__ void cp16(uint32_t s, const void* g){
    asm volatile("cp.async.cg.shared.global [%0], [%1], 16;"
                 :: "r"(s), "l"(__cvta_generic_to_global(g)) : "memory");
}

// ============================================================================
// K1: fused LN(z) + h @ [Wp|Wg|Wgate] + p*sigmoid(g).  fp16 mma (m16n8k16).
// R13 structure (single sync/tile, direct STG epilogue) + precomputed epilogue
// base pointers: per-thread columns {cb..cb+25} provably land entirely in one
// of g_a / g_b (wc<4 <=> max col 127), so all 32 store addresses are one base
// + compile-time offsets; base advances by gridDim.x*64 per tile.
// SMEM:
//   Zst (fp32 z staging, dbuf) 2 x [64][68]      = 34816 B @ 0
//   Wsm (fp16 weights) [ch2][576][32]            = 73728 B @ 34816
//   Hsm (fp16 h, dbuf) [buf2][ch2][64][32]       = 16384 B @ 108544
// ============================================================================
#define K1_SMEM 124928

__device__ __forceinline__ void k1_load_z(uint32_t smb, const float* z, int tile, int buf, int t){
    const int lr = t >> 3, lsub = t & 7;
    uint32_t dst = smb + (uint32_t)((buf*64*68 + lr*68 + lsub*8)*4);
    const float* src = z + (size_t)(tile*64 + lr)*D_IN + lsub*8;
    cp16(dst, src);
    cp16(dst + 16, src + 4);
    asm volatile("cp.async.commit_group;" ::: "memory");
}

__global__ void __launch_bounds__(512,1) k1_proj(
    const float* __restrict__ z, const float* __restrict__ lnw, const float* __restrict__ lnb,
    const float* __restrict__ Wp, const float* __restrict__ Wg, const float* __restrict__ Wgate)
{
    extern __shared__ char smc[];
    float*  Zst = (float*)smc;                    // [buf][64][68]
    __half* Wsm = (__half*)(smc + 34816);         // [ch][576][32]
    __half* Hsm = (__half*)(smc + 108544);        // [buf][ch][64][32]
    const uint32_t smb = (uint32_t)__cvta_generic_to_shared(smc);
    const int t = threadIdx.x;
    const int NT = (int)(R_TOT/64);

    // preload weights (fp16): even 8-col tiles=Wp, odd=Wg, tiles 64..71=Wgate
    for (int idx = t; idx < 576*D_IN; idx += 512){
        int k = idx / 576, n = idx - k*576;
        int T = n >> 3, ct = n & 7;
        float v;
        if (T < 64){
            int col = (T>>1)*8 + ct;
            v = (T & 1) ? Wg[k*256 + col] : Wp[k*256 + col];
        } else {
            v = Wgate[k*64 + (T-64)*8 + ct];
        }
        Wsm[(k>>5)*18432 + n*32 + (k&31)] = __float2half_rn(v);
    }

    const int lane = t & 31, w = t >> 5;
    const int wr = w >> 3, wc = w & 7;          // 2 warp-rows x 8 warp-cols
    const int grp = lane >> 2, tg = lane & 3;
    const int lr = t >> 3, lsub = t & 7;        // LN: 8 threads / row
    const float lw0 = __ldg(lnw+lsub*8+0), lw1 = __ldg(lnw+lsub*8+1),
                lw2 = __ldg(lnw+lsub*8+2), lw3 = __ldg(lnw+lsub*8+3),
                lw4 = __ldg(lnw+lsub*8+4), lw5 = __ldg(lnw+lsub*8+5),
                lw6 = __ldg(lnw+lsub*8+6), lw7 = __ldg(lnw+lsub*8+7);
    const float lb0 = __ldg(lnb+lsub*8+0), lb1 = __ldg(lnb+lsub*8+1),
                lb2 = __ldg(lnb+lsub*8+2), lb3 = __ldg(lnb+lsub*8+3),
                lb4 = __ldg(lnb+lsub*8+4), lb5 = __ldg(lnb+lsub*8+5),
                lb6 = __ldg(lnb+lsub*8+6), lb7 = __ldg(lnb+lsub*8+7);

    const int mbase = wr*32;
    // precomputed epilogue pointers (advance per tile)
    const int cb = wc*32 + tg*2;                 // cols = cb+{0,1,8,9,16,17,24,25}
    __half* pab = (wc < 4) ? (g_a + (size_t)cb*R_TOT) : (g_b + (size_t)(cb-128)*R_TOT);
    pab += (size_t)blockIdx.x*64 + mbase + grp;
    __half* pg  = g_gate + ((size_t)blockIdx.x*64 + mbase + grp)*D_IN + (wc*8 + tg*2);
    const size_t pab_step = (size_t)gridDim.x*64;
    const size_t pg_step  = (size_t)gridDim.x*64*D_IN;

    int buf = 0;
    if ((int)blockIdx.x < NT) k1_load_z(smb, z, blockIdx.x, 0, t);

    for (int tile = blockIdx.x; tile < NT;
         tile += gridDim.x, buf ^= 1, pab += pab_step, pg += pg_step){
        asm volatile("cp.async.wait_group 0;" ::: "memory");

        // ---- LayerNorm own 8 elements -> fp16 chunked Hsm ----
        {
            const float* zp = Zst + buf*64*68 + lr*68 + lsub*8;
            float4 v0 = *(const float4*)zp;
            float4 v1 = *(const float4*)(zp + 4);
            float s = v0.x+v0.y+v0.z+v0.w + v1.x+v1.y+v1.z+v1.w;
            float q = v0.x*v0.x+v0.y*v0.y+v0.z*v0.z+v0.w*v0.w
                    + v1.x*v1.x+v1.y*v1.y+v1.z*v1.z+v1.w*v1.w;
            s += __shfl_xor_sync(0xffffffffu, s, 1); q += __shfl_xor_sync(0xffffffffu, q, 1);
            s += __shfl_xor_sync(0xffffffffu, s, 2); q += __shfl_xor_sync(0xffffffffu, q, 2);
            s += __shfl_xor_sync(0xffffffffu, s, 4); q += __shfl_xor_sync(0xffffffffu, q, 4);
            float mu = s * (1.0f/64.0f);
            float rstd = rsqrtf(q*(1.0f/64.0f) - mu*mu + LN_EPS);
            __half2 h0 = __floats2half2_rn((v0.x-mu)*rstd*lw0 + lb0, (v0.y-mu)*rstd*lw1 + lb1);
            __half2 h1 = __floats2half2_rn((v0.z-mu)*rstd*lw2 + lb2, (v0.w-mu)*rstd*lw3 + lb3);
            __half2 h2 = __floats2half2_rn((v1.x-mu)*rstd*lw4 + lb4, (v1.y-mu)*rstd*lw5 + lb5);
            __half2 h3 = __floats2half2_rn((v1.z-mu)*rstd*lw6 + lb6, (v1.w-mu)*rstd*lw7 + lb7);
            __half2* hp = (__half2*)(Hsm + buf*4096 + (lsub>>2)*2048 + lr*32 + (lsub&3)*8);
            hp[0] = h0; hp[1] = h1; hp[2] = h2; hp[3] = h3;
        }
        __syncthreads();

        // prefetch next tile while mma runs
        int ntile = tile + gridDim.x;
        if (ntile < NT) k1_load_z(smb, z, ntile, buf^1, t);

        float acc[9][2][4];
        #pragma unroll
        for (int a1=0;a1<9;a1++)
            #pragma unroll
            for (int a2=0;a2<2;a2++)
                #pragma unroll
                for (int a3=0;a3<4;a3++) acc[a1][a2][a3]=0.f;

        const __half* Hb = Hsm + buf*4096;
        #pragma unroll
        for (int ch=0; ch<2; ch++){
            const __half* Ha = Hb + ch*2048;
            uint4 alo[2], ahi[2];
            #pragma unroll
            for (int ms=0; ms<2; ms++){
                alo[ms] = *(const uint4*)(Ha + (mbase + ms*16 + grp)*32 + tg*8);
                ahi[ms] = *(const uint4*)(Ha + (mbase + ms*16 + 8 + grp)*32 + tg*8);
            }
            #pragma unroll
            for (int nt=0; nt<9; nt++){
                const int tileN = (nt<8) ? (wc*8+nt) : (64+wc);
                uint4 bv = *(const uint4*)(Wsm + ch*18432 + (tileN*8 + grp)*32 + tg*8);
                #pragma unroll
                for (int ms=0; ms<2; ms++){
                    mma16(acc[nt][ms], alo[ms].x, ahi[ms].x, alo[ms].y, ahi[ms].y, bv.x, bv.y);
                    mma16(acc[nt][ms], alo[ms].z, ahi[ms].z, alo[ms].w, ahi[ms].w, bv.z, bv.w);
                }
            }
        }

        // ---- epilogue: pg = P*sig(G) -> fp16, compile-time store offsets ----
        #pragma unroll
        for (int pp=0; pp<4; pp++){
            #pragma unroll
            for (int ms=0; ms<2; ms++){
                #pragma unroll
                for (int e=0; e<4; e++){
                    float av = acc[2*pp][ms][e] * sigmoid_f(acc[2*pp+1][ms][e]);
                    pab[(size_t)(pp*8 + (e&1))*R_TOT + ms*16 + ((e>>1)<<3)]
                        = __float2half_rn(av);
                }
            }
        }
        #pragma unroll
        for (int ms=0; ms<2; ms++){
            __half2 h0 = __floats2half2_rn(sigmoid_f(acc[8][ms][0]), sigmoid_f(acc[8][ms][1]));
            __half2 h1 = __floats2half2_rn(sigmoid_f(acc[8][ms][2]), sigmoid_f(acc[8][ms][3]));
            *(__half2*)(pg + (ms*16)*D_IN)     = h0;
            *(__half2*)(pg + (ms*16+8)*D_IN)   = h1;
        }
    }
}

// ============================================================================
// K2: per-channel NT GEMM OP_c = A_c @ B_c^T in fp16 (fp32 accumulate).
// 128x128x32 stages, 256 threads, 2 CTA/SM, double-buffered cp.async.
// (verified passing — unchanged)
// ============================================================================
#define K2_STAGE_H 8192
#define K2_SMEM (2*K2_STAGE_H*2)             // 32768 B

__device__ __forceinline__ void k2_load(uint32_t smb, const __half* Ag, const __half* Bg,
                                        int t, int kt, int buf){
    const int kb = kt*32;
    const uint32_t base = smb + (uint32_t)(buf*K2_STAGE_H*2);
    #pragma unroll
    for (int s=0; s<2; s++){
        int idx = t + s*256;
        int r = idx >> 2, ci = idx & 3;
        cp16(base + (uint32_t)(r*64 + ci*16),
             Ag + (size_t)r*N_SEQ + kb + ci*8);
    }
    #pragma unroll
    for (int s=0; s<2; s++){
        int idx = t + s*256;
        int r = idx >> 2, ci = idx & 3;
        cp16(base + 8192u + (uint32_t)(r*64 + ci*16),
             Bg + (size_t)r*N_SEQ + kb + ci*8);
    }
    asm volatile("cp.async.commit_group;" ::: "memory");
}

__global__ void __launch_bounds__(256,2) k2_tri()
{
    extern __shared__ __half smh[];
    const uint32_t smb = (uint32_t)__cvta_generic_to_shared(smh);
    const int c  = blockIdx.y;
    const int i0 = (blockIdx.x >> 2) * 128;
    const int j0 = (blockIdx.x & 3) * 128;
    const __half* Ag = g_a + (size_t)c*R_TOT + (size_t)i0*N_SEQ;
    const __half* Bg = g_b + (size_t)c*R_TOT + (size_t)j0*N_SEQ;

    const int t = threadIdx.x, lane = t & 31, w = t >> 5;
    const int grp = lane >> 2, tg = lane & 3;
    const int wm = (w >> 2) * 64, wn = (w & 3) * 32;

    float acc[4][4][4];
    #pragma unroll
    for (int a1=0;a1<4;a1++)
        #pragma unroll
        for (int a2=0;a2<4;a2++)
            #pragma unroll
            for (int a3=0;a3<4;a3++) acc[a1][a2][a3]=0.f;

    k2_load(smb, Ag, Bg, t, 0, 0);

    for (int kt = 0; kt < 16; kt++){
        const int buf = kt & 1;
        asm volatile("cp.async.wait_group 0;" ::: "memory");
        __syncthreads();
        if (kt < 15) k2_load(smb, Ag, Bg, t, kt+1, buf^1);

        const __half* As = smh + buf*K2_STAGE_H;
        const __half* Bs = As + 4096;

        uint4 bv[4];
        #pragma unroll
        for (int ns=0; ns<4; ns++)
            bv[ns] = *(const uint4*)(Bs + (wn + ns*8 + grp)*32 + tg*8);

        #pragma unroll
        for (int ms=0; ms<4; ms++){
            uint4 alo = *(const uint4*)(As + (wm + ms*16 + grp)*32 + tg*8);
            uint4 ahi = *(const uint4*)(As + (wm + ms*16 + 8 + grp)*32 + tg*8);
            #pragma unroll
            for (int ns=0; ns<4; ns++){
                mma16(acc[ms][ns], alo.x, ahi.x, alo.y, ahi.y, bv[ns].x, bv[ns].y);
                mma16(acc[ms][ns], alo.z, ahi.z, alo.w, ahi.w, bv[ns].z, bv[ns].w);
            }
        }
    }

    // epilogue: g_op[c][i][j] fp16
    #pragma unroll
    for (int ms=0; ms<4; ms++){
        #pragma unroll
        for (int ns=0; ns<4; ns++){
            size_t base = (size_t)c*R_TOT + (size_t)(i0+wm+ms*16+grp)*N_SEQ + (j0+wn+ns*8+tg*2);
            *(__half2*)(g_op + base)           = __floats2half2_rn(acc[ms][ns][0], acc[ms][ns][1]);
            *(__half2*)(g_op + base + 8*N_SEQ) = __floats2half2_rn(acc[ms][ns][2], acc[ms][ns][3]);
        }
    }
}

// ============================================================================
// K3: transpose 128pos x 128chan tile, LN over channels, @Wout (tf32 mma),
//     * gate (fp16), write final output.  g_op is fp16.
// ============================================================================
#define K3PAD 132
#define K3_SMEM ((128*K3PAD + 64*K3PAD)*4)   // 101376

__global__ void __launch_bounds__(256,2) k3_out(
    const float* __restrict__ lnow, const float* __restrict__ lnob,
    const float* __restrict__ Wout, float* __restrict__ outp)
{
    extern __shared__ float sm[];
    float* Op = sm;                   // [128 pos][K3PAD] channels contiguous
    float* Wsm = sm + 128*K3PAD;      // [64 n][K3PAD] k contiguous
    const int t = threadIdx.x;
    const int pos0 = blockIdx.x * 128;

    for (int idx = t; idx < 64*128; idx += 256){
        int k = idx >> 6, n = idx & 63;
        Wsm[n*K3PAD + k] = tf32f(Wout[k*64 + n]);
    }
    for (int idx = t; idx < 128*64; idx += 256){
        int c = idx >> 6, p2 = (idx & 63)*2;
        float2 v = __half22float2(*(const __half2*)(g_op + (size_t)c*R_TOT + pos0 + p2));
        Op[p2*K3PAD + c]     = v.x;
        Op[(p2+1)*K3PAD + c] = v.y;
    }
    __syncthreads();

    {
        const int r = t >> 1, h = t & 1;
        float* base = Op + r*K3PAD + h*64;
        float s = 0.f, q = 0.f;
        #pragma unroll
        for (int j=0; j<16; j++){
            float4 v = *(float4*)(base + j*4);
            s += v.x+v.y+v.z+v.w;
            q += v.x*v.x+v.y*v.y+v.z*v.z+v.w*v.w;
        }
        s += __shfl_xor_sync(0xffffffffu, s, 1);
        q += __shfl_xor_sync(0xffffffffu, q, 1);
        float mu = s * (1.0f/128.0f);
        float rstd = rsqrtf(q*(1.0f/128.0f) - mu*mu + LN_EPS);
        #pragma unroll
        for (int j=0; j<16; j++){
            float4 v = *(float4*)(base + j*4);
            int cb = h*64 + j*4;
            v.x = tf32f((v.x-mu)*rstd*__ldg(lnow+cb+0) + __ldg(lnob+cb+0));
            v.y = tf32f((v.y-mu)*rstd*__ldg(lnow+cb+1) + __ldg(lnob+cb+1));
            v.z = tf32f((v.z-mu)*rstd*__ldg(lnow+cb+2) + __ldg(lnob+cb+2));
            v.w = tf32f((v.w-mu)*rstd*__ldg(lnow+cb+3) + __ldg(lnob+cb+3));
            *(float4*)(base + j*4) = v;
        }
    }
    __syncthreads();

    const int lane = t & 31, w = t >> 5;
    const int grp = lane >> 2, tg = lane & 3;
    float acc[8][4];
    #pragma unroll
    for (int a1=0;a1<8;a1++)
        #pragma unroll
        for (int a3=0;a3<4;a3++) acc[a1][a3]=0.f;

    #pragma unroll
    for (int kc=0; kc<16; kc++){
        const int kb = kc*8 + tg;
        const float* pa = Op + (w*16 + grp)*K3PAD + kb;
        uint32_t af[4] = {
            __float_as_uint(pa[0]),
            __float_as_uint(pa[8*K3PAD]),
            __float_as_uint(pa[4]),
            __float_as_uint(pa[8*K3PAD+4])
        };
        #pragma unroll
        for (int nt=0; nt<8; nt++){
            const float* pb = Wsm + (nt*8 + grp)*K3PAD + kb;
            uint32_t bf[2] = {__float_as_uint(pb[0]), __float_as_uint(pb[4])};
            mma8(acc[nt], af, bf);
        }
    }

    #pragma unroll
    for (int nt=0; nt<8; nt++){
        const int colb = nt*8 + tg*2;
        const int r0 = pos0 + w*16 + grp;
        float2 gv0 = __half22float2(*(const __half2*)(g_gate + (size_t)r0*D_IN + colb));
        float2 gv1 = __half22float2(*(const __half2*)(g_gate + (size_t)(r0+8)*D_IN + colb));
        float2 o0 = {acc[nt][0]*gv0.x, acc[nt][1]*gv0.y};
        float2 o1 = {acc[nt][2]*gv1.x, acc[nt][3]*gv1.y};
        *(float2*)(outp + (size_t)r0*D_IN + colb)     = o0;
        *(float2*)(outp + (size_t)(r0+8)*D_IN + colb) = o1;
    }
}

// ============================================================================
extern "C" void kernel_launch(void* const* d_in, const int* in_sizes, int n_in,
                              void* d_out, int out_size) {
    (void)in_sizes; (void)n_in; (void)out_size;
    const float* z     = (const float*)d_in[0];
    const float* lniw  = (const float*)d_in[1];
    const float* lnib  = (const float*)d_in[2];
    const float* Wp    = (const float*)d_in[3];
    const float* Wg    = (const float*)d_in[4];
    const float* lnow  = (const float*)d_in[5];
    const float* lnob  = (const float*)d_in[6];
    const float* Wout  = (const float*)d_in[7];
    const float* Wgate = (const float*)d_in[8];
    float* outp = (float*)d_out;

    cudaFuncSetAttribute(k1_proj, cudaFuncAttributeMaxDynamicSharedMemorySize, K1_SMEM);
    cudaFuncSetAttribute(k2_tri,  cudaFuncAttributeMaxDynamicSharedMemorySize, K2_SMEM);
    cudaFuncSetAttribute(k3_out,  cudaFuncAttributeMaxDynamicSharedMemorySize, K3_SMEM);

    k1_proj<<<148, 512, K1_SMEM>>>(z, lniw, lnib, Wp, Wg, Wgate);
    k2_tri<<<dim3(16,128,1), 256, K2_SMEM>>>();
    k3_out<<<2048, 256, K3_SMEM>>>(lnow, lnob, Wout, outp);
}